// round 10
// baseline (speedup 1.0000x reference)
#include <cuda_runtime.h>
#include <cuda_fp16.h>
#include <cstdint>

// ---------------- problem config ----------------
#define M_TOT 8192
#define K_TOT 4096
#define N_TOT 16384
#define BM 128
#define BN 128
#define BK 32
#define K_ITERS (K_TOT / BK)        // 128
#define MTILES (M_TOT / BM)         // 64
#define NTILES (N_TOT / BN)         // 128
#define STAGES 6
#define A_STAGE_BYTES (BM * BK * 2)  // 8192
#define B_STAGE_BYTES (BN * BK * 2)  // 8192
#define STAGE_BYTES (A_STAGE_BYTES + B_STAGE_BYTES) // 16384
#define SMEM_TOTAL (STAGES * STAGE_BYTES)           // 98304 (2 CTAs/SM -> 192KB <= 228KB)

// Fragment-ordered scratch:
// A: [kblk=256][mblk=512][lane=32][uint4]  (a0,a1,a2,a3) = 64 MB
// B: [kblk=256][nblk=2048][lane=32][uint2] (b0,b1)       = 128 MB
static __device__ __align__(1024) char g_A[(size_t)256 * 512 * 32 * 16];
static __device__ __align__(1024) char g_B[(size_t)256 * 2048 * 32 * 8];
static __device__ float g_RS[M_TOT];

// ---------------- helpers ----------------
__device__ __forceinline__ uint32_t smem_u32(const void* p) {
    uint32_t a;
    asm("{ .reg .u64 t; cvta.to.shared.u64 t, %1; cvt.u32.u64 %0, t; }" : "=r"(a) : "l"(p));
    return a;
}
__device__ __forceinline__ void cp_async16(uint32_t dst, const void* src) {
    asm volatile("cp.async.cg.shared.global [%0], [%1], 16;" :: "r"(dst), "l"(src) : "memory");
}
__device__ __forceinline__ void cp_commit() {
    asm volatile("cp.async.commit_group;" ::: "memory");
}
__device__ __forceinline__ void cp_wait4() {
    asm volatile("cp.async.wait_group 4;" ::: "memory");
}
__device__ __forceinline__ void lds128(uint32_t* r, uint32_t a) {
    asm volatile("ld.shared.v4.u32 {%0,%1,%2,%3}, [%4];"
                 : "=r"(r[0]), "=r"(r[1]), "=r"(r[2]), "=r"(r[3]) : "r"(a));
}
__device__ __forceinline__ void lds64(uint32_t* r, uint32_t a) {
    asm volatile("ld.shared.v2.u32 {%0,%1}, [%2];" : "=r"(r[0]), "=r"(r[1]) : "r"(a));
}
__device__ __forceinline__ void mma16816(float* c, const uint32_t* a, const uint32_t* b) {
    asm volatile(
        "mma.sync.aligned.m16n8k16.row.col.f32.f16.f16.f32 "
        "{%0,%1,%2,%3}, {%4,%5,%6,%7}, {%8,%9}, {%0,%1,%2,%3};"
        : "+f"(c[0]), "+f"(c[1]), "+f"(c[2]), "+f"(c[3])
        : "r"(a[0]), "r"(a[1]), "r"(a[2]), "r"(a[3]), "r"(b[0]), "r"(b[1]));
}
__device__ __forceinline__ uint32_t h2(float x, float y) {
    __half2 h = __floats2half2_rn(x, y);
    return *(uint32_t*)&h;
}

// ---------------- prep: x fp32 -> fp16 A-fragments ----------------
__global__ void prep_a_k(const float* __restrict__ x) {
    uint32_t u = blockIdx.x * blockDim.x + threadIdx.x;
    uint32_t lane = u & 31, mblk = (u >> 5) & 511, kblk = u >> 14;
    uint32_t g = lane >> 2, t = lane & 3;
    const float* base = x + (size_t)(mblk * 16 + g) * K_TOT + kblk * 16;
    float2 p0 = *(const float2*)(base + 2 * t);
    float2 p2 = *(const float2*)(base + 2 * t + 8);
    const float* base8 = base + 8 * K_TOT;
    float2 p1 = *(const float2*)(base8 + 2 * t);
    float2 p3 = *(const float2*)(base8 + 2 * t + 8);
    uint4 w;
    w.x = h2(p0.x, p0.y);
    w.y = h2(p1.x, p1.y);
    w.z = h2(p2.x, p2.y);
    w.w = h2(p3.x, p3.y);
    *(uint4*)(g_A + (size_t)u * 16) = w;
}

// ---------------- prep: packed nibbles -> fp16 B-fragments (exact) ----------------
__global__ void prep_b_k(const int* __restrict__ p) {
    uint32_t u = blockIdx.x * blockDim.x + threadIdx.x;
    uint32_t lane = u & 31, nblk = (u >> 5) & 2047, kblk = u >> 16;
    uint32_t g = lane >> 2, t = lane & 3;
    uint32_t o = nblk * 8 + g;
    const int* row = p + (size_t)o * (K_TOT / 2) + kblk * 8 + t;
    int lo = row[0];
    int hi = row[4];
    uint2 w;
    w.x = h2((float)(lo & 15), (float)((lo >> 4) & 15));
    w.y = h2((float)(hi & 15), (float)((hi >> 4) & 15));
    *(uint2*)(g_B + (size_t)u * 8) = w;
}

// ---------------- exact fp32 row sums of x ----------------
__global__ void rowsum_k(const float* __restrict__ x) {
    __shared__ float red[4];
    int m = blockIdx.x;
    const float* row = x + (size_t)m * K_TOT;
    float s = 0.f;
    for (int k = threadIdx.x * 4; k < K_TOT; k += blockDim.x * 4) {
        float4 v = *(const float4*)(row + k);
        s += v.x + v.y + v.z + v.w;
    }
    #pragma unroll
    for (int o = 16; o; o >>= 1) s += __shfl_xor_sync(0xFFFFFFFFu, s, o);
    if ((threadIdx.x & 31) == 0) red[threadIdx.x >> 5] = s;
    __syncthreads();
    if (threadIdx.x == 0) g_RS[m] = red[0] + red[1] + red[2] + red[3];
}

// ---------------- GEMM: 128 thr/CTA, 2 CTAs/SM, warp tile 64x64, BK=32, 6 stages ----------------
__global__ void __launch_bounds__(128, 2) gemm_k(
    const float* __restrict__ scale, const float* __restrict__ zp,
    const float* __restrict__ bias, float* __restrict__ out)
{
    extern __shared__ __align__(1024) char smem[];
    const uint32_t sbase = smem_u32(smem);
    const int tid = threadIdx.x, wid = tid >> 5, lane = tid & 31;
    const int wm = wid & 1, wn = wid >> 1;          // 2 x 2 warp grid, warp tile 64x64
    const uint32_t g = lane >> 2, t = lane & 3;

    // grouped rasterization: 8 m-tiles per group for L2 reuse
    const int GROUP = 8, TPG = GROUP * NTILES;      // 1024
    int bid = blockIdx.x;
    int grp = bid / TPG, rem = bid % TPG;
    int mt = grp * GROUP + (rem & (GROUP - 1));
    int nt = rem / GROUP;

    const char* gA = g_A + (size_t)mt * 8 * 512;    // + kblk*262144 per k16-block
    const char* gB = g_B + (size_t)nt * 16 * 256;   // + kblk*524288 per k16-block

    // stage copy: iter j -> stage j % STAGES. 128 threads: A 4 chunks, B 4 chunks.
    auto issue = [&](int j) {
        uint32_t sA = sbase + (j % STAGES) * STAGE_BYTES;
        size_t kbase = (size_t)(j * 2);
        #pragma unroll
        for (int r = 0; r < 4; r++) {               // A: 512 x 16B chunks
            uint32_t c = tid + 128 * r;
            uint32_t kk = c >> 8, off = (c & 255) * 16;
            cp_async16(sA + c * 16, gA + (kbase + kk) * 262144 + off);
        }
        #pragma unroll
        for (int r = 0; r < 4; r++) {               // B: 512 x 16B chunks (16 nblk * 256B per kk)
            uint32_t c = tid + 128 * r;
            uint32_t kk = c >> 8, off = (c & 255) * 16;
            cp_async16(sA + A_STAGE_BYTES + c * 16, gB + (kbase + kk) * 524288 + off);
        }
    };

    float acc[4][8][4];
    #pragma unroll
    for (int mi = 0; mi < 4; mi++)
        #pragma unroll
        for (int nj = 0; nj < 8; nj++)
            #pragma unroll
            for (int e = 0; e < 4; e++) acc[mi][nj][e] = 0.f;

    #pragma unroll
    for (int j = 0; j < STAGES - 1; j++) { issue(j); cp_commit(); }

    for (int i = 0; i < K_ITERS; i++) {
        cp_wait4();
        __syncthreads();
        uint32_t sA = sbase + (i % STAGES) * STAGE_BYTES;
        if (i + STAGES - 1 < K_ITERS) issue(i + STAGES - 1);
        cp_commit();

        #pragma unroll
        for (int kk = 0; kk < 2; kk++) {
            uint32_t a[4][4], b[8][2];
            #pragma unroll
            for (int mi = 0; mi < 4; mi++) {
                uint32_t idx = kk * 8 + wm * 4 + mi;
                lds128(a[mi], sA + (idx * 32 + lane) * 16);
            }
            #pragma unroll
            for (int nj = 0; nj < 8; nj++) {
                uint32_t idx = kk * 16 + wn * 8 + nj;
                lds64(b[nj], sA + A_STAGE_BYTES + (idx * 32 + lane) * 8);
            }
            #pragma unroll
            for (int mi = 0; mi < 4; mi++)
                #pragma unroll
                for (int nj = 0; nj < 8; nj++)
                    mma16816(acc[mi][nj], a[mi], b[nj]);
        }
    }

    // epilogue: out = scale*acc + zero*rowsum(x) + bias   (all fp32, exact terms)
    #pragma unroll
    for (int mi = 0; mi < 4; mi++) {
        int r0 = mt * BM + wm * 64 + mi * 16 + g;
        int r1 = r0 + 8;
        float rs0 = g_RS[r0], rs1 = g_RS[r1];
        float* o0 = out + (size_t)r0 * N_TOT;
        float* o1 = out + (size_t)r1 * N_TOT;
        #pragma unroll
        for (int nj = 0; nj < 8; nj++) {
            int cb = nt * BN + wn * 64 + nj * 8 + 2 * t;
            float2 sc = *(const float2*)(scale + cb);
            float2 zq = *(const float2*)(zp + cb);
            float2 bb = *(const float2*)(bias + cb);
            float2 v0, v1;
            v0.x = sc.x * acc[mi][nj][0] + zq.x * rs0 + bb.x;
            v0.y = sc.y * acc[mi][nj][1] + zq.y * rs0 + bb.y;
            v1.x = sc.x * acc[mi][nj][2] + zq.x * rs1 + bb.x;
            v1.y = sc.y * acc[mi][nj][3] + zq.y * rs1 + bb.y;
            *(float2*)(o0 + cb) = v0;
            *(float2*)(o1 + cb) = v1;
        }
    }
}

// ---------------- host launcher ----------------
extern "C" void kernel_launch(void* const* d_in, const int* in_sizes, int n_in,
                              void* d_out, int out_size) {
    (void)in_sizes; (void)n_in; (void)out_size;
    const float* x      = (const float*)d_in[0];
    const int*   packed = (const int*)d_in[1];
    const float* scale  = (const float*)d_in[2];
    const float* zp     = (const float*)d_in[3];
    const float* bias   = (const float*)d_in[4];
    float* out = (float*)d_out;

    prep_a_k<<<16384, 256>>>(x);        // 4.19M threads
    prep_b_k<<<65536, 256>>>(packed);   // 16.8M threads
    rowsum_k<<<M_TOT, 128>>>(x);
    cudaFuncSetAttribute(gemm_k, cudaFuncAttributeMaxDynamicSharedMemorySize, SMEM_TOTAL);
    gemm_k<<<MTILES * NTILES, 128, SMEM_TOTAL>>>(scale, zp, bias, out);
}

// round 11
// speedup vs baseline: 1.5392x; 1.5392x over previous
#include <cuda_runtime.h>
#include <cuda_fp16.h>
#include <cstdint>

// ---------------- problem config ----------------
#define M_TOT 8192
#define K_TOT 4096
#define N_TOT 16384
#define BM 128
#define BN 128
#define BK 32
#define K_ITERS (K_TOT / BK)        // 128
#define MTILES (M_TOT / BM)         // 64
#define NTILES (N_TOT / BN)         // 128
#define STAGES 5
#define A_STAGE_BYTES (BM * BK * 2)  // 8192
#define B_STAGE_BYTES (BN * BK * 2)  // 8192
#define STAGE_BYTES (A_STAGE_BYTES + B_STAGE_BYTES) // 16384
#define SMEM_TOTAL (STAGES * STAGE_BYTES)           // 81920 (2 CTAs/SM -> 160KB <= 228KB)

// Fragment-ordered scratch:
// A: [kblk=256][mblk=512][lane=32][uint4]  (a0,a1,a2,a3) = 64 MB
// B: [kblk=256][nblk=2048][lane=32][uint2] (b0,b1)       = 128 MB
static __device__ __align__(1024) char g_A[(size_t)256 * 512 * 32 * 16];
static __device__ __align__(1024) char g_B[(size_t)256 * 2048 * 32 * 8];
static __device__ float g_RS[M_TOT];

// ---------------- helpers ----------------
__device__ __forceinline__ uint32_t smem_u32(const void* p) {
    uint32_t a;
    asm("{ .reg .u64 t; cvta.to.shared.u64 t, %1; cvt.u32.u64 %0, t; }" : "=r"(a) : "l"(p));
    return a;
}
__device__ __forceinline__ void cp_async16(uint32_t dst, const void* src) {
    asm volatile("cp.async.cg.shared.global [%0], [%1], 16;" :: "r"(dst), "l"(src) : "memory");
}
__device__ __forceinline__ void cp_commit() {
    asm volatile("cp.async.commit_group;" ::: "memory");
}
__device__ __forceinline__ void cp_wait3() {
    asm volatile("cp.async.wait_group 3;" ::: "memory");
}
__device__ __forceinline__ void lds128(uint32_t* r, uint32_t a) {
    asm volatile("ld.shared.v4.u32 {%0,%1,%2,%3}, [%4];"
                 : "=r"(r[0]), "=r"(r[1]), "=r"(r[2]), "=r"(r[3]) : "r"(a));
}
__device__ __forceinline__ void lds64(uint32_t* r, uint32_t a) {
    asm volatile("ld.shared.v2.u32 {%0,%1}, [%2];" : "=r"(r[0]), "=r"(r[1]) : "r"(a));
}
__device__ __forceinline__ void mma16816(float* c, const uint32_t* a, const uint32_t* b) {
    asm volatile(
        "mma.sync.aligned.m16n8k16.row.col.f32.f16.f16.f32 "
        "{%0,%1,%2,%3}, {%4,%5,%6,%7}, {%8,%9}, {%0,%1,%2,%3};"
        : "+f"(c[0]), "+f"(c[1]), "+f"(c[2]), "+f"(c[3])
        : "r"(a[0]), "r"(a[1]), "r"(a[2]), "r"(a[3]), "r"(b[0]), "r"(b[1]));
}
__device__ __forceinline__ uint32_t h2(float x, float y) {
    __half2 h = __floats2half2_rn(x, y);
    return *(uint32_t*)&h;
}

// ---------------- prep: x fp32 -> fp16 A-fragments ----------------
__global__ void prep_a_k(const float* __restrict__ x) {
    uint32_t u = blockIdx.x * blockDim.x + threadIdx.x;
    uint32_t lane = u & 31, mblk = (u >> 5) & 511, kblk = u >> 14;
    uint32_t g = lane >> 2, t = lane & 3;
    const float* base = x + (size_t)(mblk * 16 + g) * K_TOT + kblk * 16;
    float2 p0 = *(const float2*)(base + 2 * t);
    float2 p2 = *(const float2*)(base + 2 * t + 8);
    const float* base8 = base + 8 * K_TOT;
    float2 p1 = *(const float2*)(base8 + 2 * t);
    float2 p3 = *(const float2*)(base8 + 2 * t + 8);
    uint4 w;
    w.x = h2(p0.x, p0.y);
    w.y = h2(p1.x, p1.y);
    w.z = h2(p2.x, p2.y);
    w.w = h2(p3.x, p3.y);
    *(uint4*)(g_A + (size_t)u * 16) = w;
}

// ---------------- prep: packed nibbles -> fp16 B-fragments (exact) ----------------
__global__ void prep_b_k(const int* __restrict__ p) {
    uint32_t u = blockIdx.x * blockDim.x + threadIdx.x;
    uint32_t lane = u & 31, nblk = (u >> 5) & 2047, kblk = u >> 16;
    uint32_t g = lane >> 2, t = lane & 3;
    uint32_t o = nblk * 8 + g;
    const int* row = p + (size_t)o * (K_TOT / 2) + kblk * 8 + t;
    int lo = row[0];
    int hi = row[4];
    uint2 w;
    w.x = h2((float)(lo & 15), (float)((lo >> 4) & 15));
    w.y = h2((float)(hi & 15), (float)((hi >> 4) & 15));
    *(uint2*)(g_B + (size_t)u * 8) = w;
}

// ---------------- exact fp32 row sums of x ----------------
__global__ void rowsum_k(const float* __restrict__ x) {
    __shared__ float red[4];
    int m = blockIdx.x;
    const float* row = x + (size_t)m * K_TOT;
    float s = 0.f;
    for (int k = threadIdx.x * 4; k < K_TOT; k += blockDim.x * 4) {
        float4 v = *(const float4*)(row + k);
        s += v.x + v.y + v.z + v.w;
    }
    #pragma unroll
    for (int o = 16; o; o >>= 1) s += __shfl_xor_sync(0xFFFFFFFFu, s, o);
    if ((threadIdx.x & 31) == 0) red[threadIdx.x >> 5] = s;
    __syncthreads();
    if (threadIdx.x == 0) g_RS[m] = red[0] + red[1] + red[2] + red[3];
}

// ---------------- GEMM: 128 thr/CTA, 2 CTAs/SM, warp tile 64x64, BK=32, 5 stages ----------------
__global__ void __launch_bounds__(128, 2) gemm_k(
    const float* __restrict__ scale, const float* __restrict__ zp,
    const float* __restrict__ bias, float* __restrict__ out)
{
    extern __shared__ __align__(1024) char smem[];
    const uint32_t sbase = smem_u32(smem);
    const int tid = threadIdx.x, wid = tid >> 5, lane = tid & 31;
    const int wm = wid & 1, wn = wid >> 1;          // 2 x 2 warp grid, warp tile 64x64
    const uint32_t g = lane >> 2, t = lane & 3;

    // grouped rasterization: 8 m-tiles per group for L2 reuse
    const int GROUP = 8, TPG = GROUP * NTILES;      // 1024
    int bid = blockIdx.x;
    int grp = bid / TPG, rem = bid % TPG;
    int mt = grp * GROUP + (rem & (GROUP - 1));
    int nt = rem / GROUP;

    const char* gA = g_A + (size_t)mt * 8 * 512;    // + kblk*262144 per k16-block
    const char* gB = g_B + (size_t)nt * 16 * 256;   // + kblk*524288 per k16-block

    // stage copy: iter j -> stage j % STAGES. 128 threads: A 4 chunks, B 4 chunks.
    auto issue = [&](int j) {
        uint32_t sA = sbase + (j % STAGES) * STAGE_BYTES;
        size_t kbase = (size_t)(j * 2);
        #pragma unroll
        for (int r = 0; r < 4; r++) {               // A: 512 x 16B chunks
            uint32_t c = tid + 128 * r;
            uint32_t kk = c >> 8, off = (c & 255) * 16;
            cp_async16(sA + c * 16, gA + (kbase + kk) * 262144 + off);
        }
        #pragma unroll
        for (int r = 0; r < 4; r++) {               // B: 512 x 16B chunks (16 nblk * 256B per kk)
            uint32_t c = tid + 128 * r;
            uint32_t kk = c >> 8, off = (c & 255) * 16;
            cp_async16(sA + A_STAGE_BYTES + c * 16, gB + (kbase + kk) * 524288 + off);
        }
    };

    float acc[4][8][4];
    #pragma unroll
    for (int mi = 0; mi < 4; mi++)
        #pragma unroll
        for (int nj = 0; nj < 8; nj++)
            #pragma unroll
            for (int e = 0; e < 4; e++) acc[mi][nj][e] = 0.f;

    #pragma unroll
    for (int j = 0; j < STAGES - 1; j++) { issue(j); cp_commit(); }

    for (int i = 0; i < K_ITERS; i++) {
        cp_wait3();
        __syncthreads();
        uint32_t sA = sbase + (i % STAGES) * STAGE_BYTES;
        if (i + STAGES - 1 < K_ITERS) issue(i + STAGES - 1);
        cp_commit();

        #pragma unroll
        for (int kk = 0; kk < 2; kk++) {
            uint32_t a[4][4], b[8][2];
            #pragma unroll
            for (int mi = 0; mi < 4; mi++) {
                uint32_t idx = kk * 8 + wm * 4 + mi;
                lds128(a[mi], sA + (idx * 32 + lane) * 16);
            }
            #pragma unroll
            for (int nj = 0; nj < 8; nj++) {
                uint32_t idx = kk * 16 + wn * 8 + nj;
                lds64(b[nj], sA + A_STAGE_BYTES + (idx * 32 + lane) * 8);
            }
            #pragma unroll
            for (int mi = 0; mi < 4; mi++)
                #pragma unroll
                for (int nj = 0; nj < 8; nj++)
                    mma16816(acc[mi][nj], a[mi], b[nj]);
        }
    }

    // epilogue: out = scale*acc + zero*rowsum(x) + bias   (all fp32, exact terms)
    #pragma unroll
    for (int mi = 0; mi < 4; mi++) {
        int r0 = mt * BM + wm * 64 + mi * 16 + g;
        int r1 = r0 + 8;
        float rs0 = g_RS[r0], rs1 = g_RS[r1];
        float* o0 = out + (size_t)r0 * N_TOT;
        float* o1 = out + (size_t)r1 * N_TOT;
        #pragma unroll
        for (int nj = 0; nj < 8; nj++) {
            int cb = nt * BN + wn * 64 + nj * 8 + 2 * t;
            float2 sc = *(const float2*)(scale + cb);
            float2 zq = *(const float2*)(zp + cb);
            float2 bb = *(const float2*)(bias + cb);
            float2 v0, v1;
            v0.x = sc.x * acc[mi][nj][0] + zq.x * rs0 + bb.x;
            v0.y = sc.y * acc[mi][nj][1] + zq.y * rs0 + bb.y;
            v1.x = sc.x * acc[mi][nj][2] + zq.x * rs1 + bb.x;
            v1.y = sc.y * acc[mi][nj][3] + zq.y * rs1 + bb.y;
            *(float2*)(o0 + cb) = v0;
            *(float2*)(o1 + cb) = v1;
        }
    }
}

// ---------------- host launcher ----------------
extern "C" void kernel_launch(void* const* d_in, const int* in_sizes, int n_in,
                              void* d_out, int out_size) {
    (void)in_sizes; (void)n_in; (void)out_size;
    const float* x      = (const float*)d_in[0];
    const int*   packed = (const int*)d_in[1];
    const float* scale  = (const float*)d_in[2];
    const float* zp     = (const float*)d_in[3];
    const float* bias   = (const float*)d_in[4];
    float* out = (float*)d_out;

    prep_a_k<<<16384, 256>>>(x);        // 4.19M threads
    prep_b_k<<<65536, 256>>>(packed);   // 16.8M threads
    rowsum_k<<<M_TOT, 128>>>(x);
    cudaFuncSetAttribute(gemm_k, cudaFuncAttributeMaxDynamicSharedMemorySize, SMEM_TOTAL);
    gemm_k<<<MTILES * NTILES, 128, SMEM_TOTAL>>>(scale, zp, bias, out);
}